// round 3
// baseline (speedup 1.0000x reference)
#include <cuda_runtime.h>

#define CC 16
#define HH 512
#define WW 384
#define HWSZ (HH*WW)
#define NK 16
#define NITER 4

// ---------------- device scratch (static, no allocation) ----------------
__device__ float2 g_kbuf[CC*HWSZ];
__device__ float2 g_image[HWSZ];
__device__ float2 g_Ahb[HWSZ];
__device__ float2 g_d[HWSZ];
__device__ float2 g_Qd[HWSZ];
__device__ float  g_wsum[HWSZ];
__device__ float  g_act0[NK*HWSZ];
__device__ float  g_act1[NK*HWSZ];
__device__ float2 g_M1[WW*WW];
__device__ float2 g_M2[WW*WW];
__device__ float  g_bnscale[NK];
__device__ float  g_bnshift[NK];
__device__ float2 g_alpha;

__device__ __forceinline__ float2 cmulf(float2 a, float2 b) {
    return make_float2(a.x*b.x - a.y*b.y, a.x*b.y + a.y*b.x);
}

// ---------------- inverse FFT, column direction, N=512 ----------------
// ortho: scale 1/sqrt(512).  inverse => twiddle sign +1.
__global__ void ifft_col512(const float2* __restrict__ in) {
    __shared__ float2 s[512];
    int col = blockIdx.x, coil = blockIdx.y;
    const float2* p = in + (size_t)coil*HWSZ;
    float2* q = g_kbuf + (size_t)coil*HWSZ;
    int t = threadIdx.x; // 256
    for (int k = t; k < 512; k += 256) {
        int br = __brev((unsigned)k) >> 23; // 9-bit reversal
        s[br] = p[(size_t)k*WW + col];
    }
    __syncthreads();
    int lh = 0;
    for (int len = 2; len <= 512; len <<= 1, lh++) {
        int half = len >> 1;
        int j = t & (half - 1);
        int i0 = ((t >> lh) << (lh + 1)) + j;
        int i1 = i0 + half;
        float ang = 6.28318530717958647692f * (float)j / (float)len;
        float sn, cs; sincosf(ang, &sn, &cs);
        float2 u = s[i0], v = s[i1];
        float2 vw = make_float2(v.x*cs - v.y*sn, v.x*sn + v.y*cs);
        s[i0] = make_float2(u.x + vw.x, u.y + vw.y);
        s[i1] = make_float2(u.x - vw.x, u.y - vw.y);
        __syncthreads();
    }
    const float sc = 0.04419417382415922f; // 1/sqrt(512)
    for (int k = t; k < 512; k += 256) {
        float2 v = s[k];
        q[(size_t)k*WW + col] = make_float2(v.x*sc, v.y*sc);
    }
}

// ---------------- inverse FFT, row direction, N=384 = 3 * 128 ----------------
__global__ void ifft_row384() {
    __shared__ float2 f[3][128];
    int row = blockIdx.x, coil = blockIdx.y;
    float2* p = g_kbuf + (size_t)coil*HWSZ + (size_t)row*WW;
    int t = threadIdx.x; // 128
    int br = __brev((unsigned)t) >> 25; // 7-bit reversal
    f[0][br] = p[3*t + 0];
    f[1][br] = p[3*t + 1];
    f[2][br] = p[3*t + 2];
    __syncthreads();
    int lh = 0;
    for (int len = 2; len <= 128; len <<= 1, lh++) {
        int half = len >> 1;
        for (int bt = t; bt < 192; bt += 128) {
            int sub = bt >> 6;       // which 128-pt FFT (0..2)
            int u = bt & 63;         // butterfly index
            int j = u & (half - 1);
            int i0 = ((u >> lh) << (lh + 1)) + j;
            float ang = 6.28318530717958647692f * (float)j / (float)len;
            float sn, cs; sincosf(ang, &sn, &cs);
            float2 a = f[sub][i0], b = f[sub][i0 + half];
            float2 bw = make_float2(b.x*cs - b.y*sn, b.x*sn + b.y*cs);
            f[sub][i0] = make_float2(a.x + bw.x, a.y + bw.y);
            f[sub][i0 + half] = make_float2(a.x - bw.x, a.y - bw.y);
        }
        __syncthreads();
    }
    // radix-3 combine: X[128c + d] = sum_b w3^{bc} * W384^{bd} * F_b[d]
    float ang1 = 6.28318530717958647692f * (float)t / 384.0f;
    float sn1, cs1; sincosf(ang1, &sn1, &cs1);
    float sn2, cs2; sincosf(2.0f*ang1, &sn2, &cs2);
    float2 t0 = f[0][t];
    float2 t1 = cmulf(f[1][t], make_float2(cs1, sn1));
    float2 t2 = cmulf(f[2][t], make_float2(cs2, sn2));
    const float h3 = 0.86602540378443864676f;
    float2 w3  = make_float2(-0.5f,  h3);  // e^{+2pi i/3} (inverse)
    float2 w3b = make_float2(-0.5f, -h3);
    const float sc = 0.05103103630798288f; // 1/sqrt(384)
    float2 a1 = cmulf(w3, t1),  a2 = cmulf(w3b, t2);
    float2 b1 = cmulf(w3b, t1), b2 = cmulf(w3,  t2);
    float2 X0 = make_float2(t0.x + t1.x + t2.x, t0.y + t1.y + t2.y);
    float2 X1 = make_float2(t0.x + a1.x + a2.x, t0.y + a1.y + a2.y);
    float2 X2 = make_float2(t0.x + b1.x + b2.x, t0.y + b1.y + b2.y);
    p[t]       = make_float2(X0.x*sc, X0.y*sc);
    p[128 + t] = make_float2(X1.x*sc, X1.y*sc);
    p[256 + t] = make_float2(X2.x*sc, X2.y*sc);
}

// ---------------- decode: image = Ahb = sum_c conj(S_c)*kbuf_c ; wsum = sum|S|^2 ----
__global__ void decode_kernel(const float2* __restrict__ smaps) {
    int t = blockIdx.x*blockDim.x + threadIdx.x;
    if (t >= HWSZ) return;
    float2 acc = make_float2(0.f, 0.f);
    float ws = 0.f;
#pragma unroll
    for (int c = 0; c < CC; c++) {
        float2 s = smaps[(size_t)c*HWSZ + t];
        float2 k = g_kbuf[(size_t)c*HWSZ + t];
        acc.x += s.x*k.x + s.y*k.y;
        acc.y += s.x*k.y - s.y*k.x;
        ws += s.x*s.x + s.y*s.y;
    }
    g_image[t] = acc;
    g_Ahb[t]   = acc;
    g_wsum[t]  = ws;
}

// ---------------- conv 3x3 SAME, register-blocked ----------------
// MODE 0: input = g_image interleaved (2 ch), output relu(conv+bias) -> planar
// MODE 1: planar in -> planar out, conv+bias only (pre-BN)
// MODE 2: planar in (16ch) -> residual: g_image -= conv (2 ch)
template<int CIN, int COUT, int MODE>
__global__ void __launch_bounds__(128) conv3x3(int inbuf, const float* __restrict__ wt,
                                               const float* __restrict__ bias, int outbuf) {
    constexpr int CCH = (CIN < 4) ? CIN : 4;
    __shared__ float tile[CCH][18][34];
    __shared__ float wsh[COUT*CIN*9];
    int tx = threadIdx.x, ty = threadIdx.y;
    int tid = ty*32 + tx;
    int w0 = blockIdx.x*32, h0 = blockIdx.y*16;

    const float* in = (MODE == 0) ? (const float*)g_image
                                  : (inbuf ? g_act1 : g_act0);
    float* out = outbuf ? g_act1 : g_act0;

    for (int i = tid; i < COUT*CIN*9; i += 128) wsh[i] = wt[i];

    float acc[4][COUT];
#pragma unroll
    for (int p = 0; p < 4; p++)
#pragma unroll
        for (int co = 0; co < COUT; co++) acc[p][co] = bias[co];

    for (int c0 = 0; c0 < CIN; c0 += CCH) {
        __syncthreads();
        for (int i = tid; i < CCH*18*34; i += 128) {
            int ci = i / (18*34); int r = i % (18*34);
            int rr = r / 34, cc = r % 34;
            int gh = h0 - 1 + rr, gw = w0 - 1 + cc;
            float v = 0.f;
            if (gh >= 0 && gh < HH && gw >= 0 && gw < WW) {
                int pix = gh*WW + gw;
                v = (MODE == 0) ? in[2*pix + (c0 + ci)] : in[(size_t)(c0 + ci)*HWSZ + pix];
            }
            tile[ci][rr][cc] = v;
        }
        __syncthreads();
#pragma unroll
        for (int ci = 0; ci < CCH; ci++) {
            float v[6][3];
#pragma unroll
            for (int rr = 0; rr < 6; rr++)
#pragma unroll
                for (int cc = 0; cc < 3; cc++)
                    v[rr][cc] = tile[ci][ty*4 + rr][tx + cc];
            for (int co = 0; co < COUT; co++) {
                const float* wp = &wsh[((co*CIN) + (c0 + ci))*9];
                float wk[9];
#pragma unroll
                for (int k = 0; k < 9; k++) wk[k] = wp[k];
#pragma unroll
                for (int p = 0; p < 4; p++)
#pragma unroll
                    for (int kh = 0; kh < 3; kh++)
#pragma unroll
                        for (int kw = 0; kw < 3; kw++)
                            acc[p][co] += wk[kh*3 + kw] * v[p + kh][kw];
            }
        }
    }

    int wcol = w0 + tx;
#pragma unroll
    for (int p = 0; p < 4; p++) {
        int hrow = h0 + ty*4 + p;
        int pix = hrow*WW + wcol;
        if (MODE == 0) {
#pragma unroll
            for (int co = 0; co < COUT; co++)
                out[(size_t)co*HWSZ + pix] = fmaxf(acc[p][co], 0.f);
        } else if (MODE == 1) {
#pragma unroll
            for (int co = 0; co < COUT; co++)
                out[(size_t)co*HWSZ + pix] = acc[p][co];
        } else {
            float2 im = g_image[pix];
            g_image[pix] = make_float2(im.x - acc[p][0], im.y - acc[p][1]);
        }
    }
}

// ---------------- batchnorm: stats + per-channel scale/shift ----------------
__global__ void bn_stats(int buf, const float* __restrict__ g, const float* __restrict__ be) {
    __shared__ double sh[512], sh2[512];
    const float* x = buf ? g_act1 : g_act0;
    int c = blockIdx.x, t = threadIdx.x;
    double s = 0.0, s2 = 0.0;
    for (int i = t; i < HWSZ; i += 512) {
        float v = x[(size_t)c*HWSZ + i];
        s += v; s2 += (double)v*(double)v;
    }
    sh[t] = s; sh2[t] = s2; __syncthreads();
    for (int o = 256; o > 0; o >>= 1) {
        if (t < o) { sh[t] += sh[t + o]; sh2[t] += sh2[t + o]; }
        __syncthreads();
    }
    if (t == 0) {
        double m = sh[0] * (1.0 / HWSZ);
        double var = sh2[0] * (1.0 / HWSZ) - m*m;
        float sc = g[c] * rsqrtf((float)var + 1e-5f);
        g_bnscale[c] = sc;
        g_bnshift[c] = be[c] - (float)m * sc;
    }
}

__global__ void bn_apply(int buf) {
    float* x = buf ? g_act1 : g_act0;
    int idx = blockIdx.x*256 + threadIdx.x;
    if (idx >= NK*HWSZ) return;
    int c = idx >> 18;  // HWSZ = 512*384 = 196608; NOT power of two -> use divide
    c = idx / HWSZ;
    float v = x[idx];
    x[idx] = fmaxf(v*g_bnscale[c] + g_bnshift[c], 0.f);
}

// ---------------- CG pointwise: d = Ahb - (wsum+lam)*image ; Qd = (wsum+lam)*d ----
__global__ void cg_dq(const float* __restrict__ scale_layers, int it) {
    int t = blockIdx.x*blockDim.x + threadIdx.x;
    if (t >= HWSZ) return;
    float lam = scale_layers[it];
    float wl = g_wsum[t] + lam;
    float2 im = g_image[t], ahb = g_Ahb[t];
    float2 d = make_float2(ahb.x - wl*im.x, ahb.y - wl*im.y);
    g_d[t] = d;
    g_Qd[t] = make_float2(wl*d.x, wl*d.y);
}

// ---------------- Gram: M1 = D^H D, M2 = D^H Qd  (D is 512x384) ----------------
__global__ void gram_kernel() {
    __shared__ float2 sDi[16][17], sDj[16][17], sQj[16][17];
    int tx = threadIdx.x, ty = threadIdx.y;
    int i = blockIdx.y*16 + ty, j = blockIdx.x*16 + tx;
    float2 a1 = make_float2(0.f, 0.f), a2 = make_float2(0.f, 0.f);
    for (int h0 = 0; h0 < HH; h0 += 16) {
        sDi[ty][tx] = g_d[(h0 + ty)*WW + blockIdx.y*16 + tx];
        sDj[ty][tx] = g_d[(h0 + ty)*WW + blockIdx.x*16 + tx];
        sQj[ty][tx] = g_Qd[(h0 + ty)*WW + blockIdx.x*16 + tx];
        __syncthreads();
#pragma unroll
        for (int hh = 0; hh < 16; hh++) {
            float2 a = sDi[hh][ty];
            float2 b = sDj[hh][tx];
            float2 q = sQj[hh][tx];
            a1.x += a.x*b.x + a.y*b.y; a1.y += a.x*b.y - a.y*b.x;
            a2.x += a.x*q.x + a.y*q.y; a2.y += a.x*q.y - a.y*q.x;
        }
        __syncthreads();
    }
    g_M1[i*WW + j] = a1;
    g_M2[i*WW + j] = a2;
}

// ---------------- alpha = sum( M1 / M2 ), overflow-safe (double) ----------
// |M| can reach ~1e35 at iteration 4; float products would overflow to Inf ->
// Inf/Inf = NaN. Double-precision naive complex division is exact here and
// matches XLA's scaled (Smith) complex division far below the 1e-3 tolerance.
__global__ void alpha_kernel() {
    __shared__ double sr[1024], si[1024];
    int t = threadIdx.x;
    double ar = 0.0, ai = 0.0;
    for (int k = t; k < WW*WW; k += 1024) {
        float2 m1 = g_M1[k], m2 = g_M2[k];
        double m1x = m1.x, m1y = m1.y, m2x = m2.x, m2y = m2.y;
        double den = m2x*m2x + m2y*m2y;
        ar += (m1x*m2x + m1y*m2y) / den;
        ai += (m1y*m2x - m1x*m2y) / den;
    }
    sr[t] = ar; si[t] = ai; __syncthreads();
    for (int o = 512; o > 0; o >>= 1) {
        if (t < o) { sr[t] += sr[t + o]; si[t] += si[t + o]; }
        __syncthreads();
    }
    if (t == 0) g_alpha = make_float2((float)sr[0], (float)si[0]);
}

// ---------------- image += alpha * d ----------------
__global__ void update_kernel() {
    int t = blockIdx.x*blockDim.x + threadIdx.x;
    if (t >= HWSZ) return;
    float2 al = g_alpha;
    float2 d = g_d[t], im = g_image[t];
    im.x += al.x*d.x - al.y*d.y;
    im.y += al.x*d.y + al.y*d.x;
    g_image[t] = im;
}

// ---------------- crop rows [64, 448) -> out (1,384,384,2) ----------------
__global__ void crop_kernel(float2* __restrict__ out) {
    int t = blockIdx.x*blockDim.x + threadIdx.x;
    if (t >= WW*WW) return;
    int r = t / WW, c = t % WW;
    out[t] = g_image[(r + 64)*WW + c];
}

// ---------------- launch ----------------
extern "C" void kernel_launch(void* const* d_in, const int* in_sizes, int n_in,
                              void* d_out, int out_size) {
    (void)in_sizes; (void)n_in; (void)out_size;
    const float2* b_in  = (const float2*)d_in[0];
    const float2* smaps = (const float2*)d_in[1];
    const float* w0  = (const float*)d_in[2];
    const float* b0  = (const float*)d_in[3];
    const float* w1  = (const float*)d_in[4];
    const float* b1  = (const float*)d_in[5];
    const float* g1  = (const float*)d_in[6];
    const float* be1 = (const float*)d_in[7];
    const float* w2  = (const float*)d_in[8];
    const float* b2  = (const float*)d_in[9];
    const float* g2  = (const float*)d_in[10];
    const float* be2 = (const float*)d_in[11];
    const float* wl  = (const float*)d_in[12];
    const float* bl  = (const float*)d_in[13];
    const float* scl = (const float*)d_in[14];

    const int PW = (HWSZ + 255) / 256;

    // Ahb = decode(b) — the only FFTs needed (AhA collapses to pointwise)
    ifft_col512<<<dim3(WW, CC), 256>>>(b_in);
    ifft_row384<<<dim3(HH, CC), 128>>>();
    decode_kernel<<<PW, 256>>>(smaps);

    dim3 cgrid(WW/32, HH/16), cblk(32, 4);
    for (int it = 0; it < NITER; it++) {
        // DnCNN
        conv3x3<2, 16, 0><<<cgrid, cblk>>>(0, w0, b0, 0);           // image -> act0 (relu)
        conv3x3<16, 16, 1><<<cgrid, cblk>>>(0, w1, b1, 1);          // act0 -> act1
        bn_stats<<<NK, 512>>>(1, g1, be1);
        bn_apply<<<(NK*HWSZ + 255)/256, 256>>>(1);
        conv3x3<16, 16, 1><<<cgrid, cblk>>>(1, w2, b2, 0);          // act1 -> act0
        bn_stats<<<NK, 512>>>(0, g2, be2);
        bn_apply<<<(NK*HWSZ + 255)/256, 256>>>(0);
        conv3x3<16, 2, 2><<<cgrid, cblk>>>(0, wl, bl, 0);           // image -= conv(act0)
        // CG step
        cg_dq<<<PW, 256>>>(scl, it);
        gram_kernel<<<dim3(WW/16, WW/16), dim3(16, 16)>>>();
        alpha_kernel<<<1, 1024>>>();
        update_kernel<<<PW, 256>>>();
    }
    crop_kernel<<<(WW*WW + 255)/256, 256>>>((float2*)d_out);
}

// round 4
// speedup vs baseline: 3.3251x; 3.3251x over previous
#include <cuda_runtime.h>

#define CC 16
#define HH 512
#define WW 384
#define HWSZ (HH*WW)
#define NK 16
#define NITER 4
#define BN_CHUNKS 8
#define ALPHA_BLKS 576   // 576*256 == WW*WW exactly

// ---------------- device scratch (static, no allocation) ----------------
__device__ float2 g_kbuf[CC*HWSZ];
__device__ float2 g_image[HWSZ];
__device__ float2 g_Ahb[HWSZ];
__device__ float2 g_d[HWSZ];
__device__ float2 g_Qd[HWSZ];
__device__ float  g_wsum[HWSZ];
__device__ float  g_act0[NK*HWSZ];
__device__ float  g_act1[NK*HWSZ];
__device__ float2 g_M1[WW*WW];
__device__ float2 g_M2[WW*WW];
__device__ double2 g_bnpart[NK*BN_CHUNKS];
__device__ float  g_bnscale[NK];
__device__ float  g_bnshift[NK];
__device__ float2 g_apart[ALPHA_BLKS];
__device__ float2 g_alpha;

__device__ __forceinline__ float2 cmulf(float2 a, float2 b) {
    return make_float2(a.x*b.x - a.y*b.y, a.x*b.y + a.y*b.x);
}

// ---------------- inverse FFT, column direction, N=512 ----------------
__global__ void ifft_col512(const float2* __restrict__ in) {
    __shared__ float2 s[512];
    int col = blockIdx.x, coil = blockIdx.y;
    const float2* p = in + (size_t)coil*HWSZ;
    float2* q = g_kbuf + (size_t)coil*HWSZ;
    int t = threadIdx.x; // 256
    for (int k = t; k < 512; k += 256) {
        int br = __brev((unsigned)k) >> 23;
        s[br] = p[(size_t)k*WW + col];
    }
    __syncthreads();
    int lh = 0;
    for (int len = 2; len <= 512; len <<= 1, lh++) {
        int half = len >> 1;
        int j = t & (half - 1);
        int i0 = ((t >> lh) << (lh + 1)) + j;
        int i1 = i0 + half;
        float ang = 6.28318530717958647692f * (float)j / (float)len;
        float sn, cs; sincosf(ang, &sn, &cs);
        float2 u = s[i0], v = s[i1];
        float2 vw = make_float2(v.x*cs - v.y*sn, v.x*sn + v.y*cs);
        s[i0] = make_float2(u.x + vw.x, u.y + vw.y);
        s[i1] = make_float2(u.x - vw.x, u.y - vw.y);
        __syncthreads();
    }
    const float sc = 0.04419417382415922f; // 1/sqrt(512)
    for (int k = t; k < 512; k += 256) {
        float2 v = s[k];
        q[(size_t)k*WW + col] = make_float2(v.x*sc, v.y*sc);
    }
}

// ---------------- inverse FFT, row direction, N=384 = 3 * 128 ----------------
__global__ void ifft_row384() {
    __shared__ float2 f[3][128];
    int row = blockIdx.x, coil = blockIdx.y;
    float2* p = g_kbuf + (size_t)coil*HWSZ + (size_t)row*WW;
    int t = threadIdx.x; // 128
    int br = __brev((unsigned)t) >> 25;
    f[0][br] = p[3*t + 0];
    f[1][br] = p[3*t + 1];
    f[2][br] = p[3*t + 2];
    __syncthreads();
    int lh = 0;
    for (int len = 2; len <= 128; len <<= 1, lh++) {
        int half = len >> 1;
        for (int bt = t; bt < 192; bt += 128) {
            int sub = bt >> 6;
            int u = bt & 63;
            int j = u & (half - 1);
            int i0 = ((u >> lh) << (lh + 1)) + j;
            float ang = 6.28318530717958647692f * (float)j / (float)len;
            float sn, cs; sincosf(ang, &sn, &cs);
            float2 a = f[sub][i0], b = f[sub][i0 + half];
            float2 bw = make_float2(b.x*cs - b.y*sn, b.x*sn + b.y*cs);
            f[sub][i0] = make_float2(a.x + bw.x, a.y + bw.y);
            f[sub][i0 + half] = make_float2(a.x - bw.x, a.y - bw.y);
        }
        __syncthreads();
    }
    float ang1 = 6.28318530717958647692f * (float)t / 384.0f;
    float sn1, cs1; sincosf(ang1, &sn1, &cs1);
    float sn2, cs2; sincosf(2.0f*ang1, &sn2, &cs2);
    float2 t0 = f[0][t];
    float2 t1 = cmulf(f[1][t], make_float2(cs1, sn1));
    float2 t2 = cmulf(f[2][t], make_float2(cs2, sn2));
    const float h3 = 0.86602540378443864676f;
    float2 w3  = make_float2(-0.5f,  h3);
    float2 w3b = make_float2(-0.5f, -h3);
    const float sc = 0.05103103630798288f; // 1/sqrt(384)
    float2 a1 = cmulf(w3, t1),  a2 = cmulf(w3b, t2);
    float2 b1 = cmulf(w3b, t1), b2 = cmulf(w3,  t2);
    float2 X0 = make_float2(t0.x + t1.x + t2.x, t0.y + t1.y + t2.y);
    float2 X1 = make_float2(t0.x + a1.x + a2.x, t0.y + a1.y + a2.y);
    float2 X2 = make_float2(t0.x + b1.x + b2.x, t0.y + b1.y + b2.y);
    p[t]       = make_float2(X0.x*sc, X0.y*sc);
    p[128 + t] = make_float2(X1.x*sc, X1.y*sc);
    p[256 + t] = make_float2(X2.x*sc, X2.y*sc);
}

// ---------------- decode ----------------
__global__ void decode_kernel(const float2* __restrict__ smaps) {
    int t = blockIdx.x*blockDim.x + threadIdx.x;
    if (t >= HWSZ) return;
    float2 acc = make_float2(0.f, 0.f);
    float ws = 0.f;
#pragma unroll
    for (int c = 0; c < CC; c++) {
        float2 s = smaps[(size_t)c*HWSZ + t];
        float2 k = g_kbuf[(size_t)c*HWSZ + t];
        acc.x += s.x*k.x + s.y*k.y;
        acc.y += s.x*k.y - s.y*k.x;
        ws += s.x*s.x + s.y*s.y;
    }
    g_image[t] = acc;
    g_Ahb[t]   = acc;
    g_wsum[t]  = ws;
}

// ---------------- conv 3x3 SAME, register-blocked ----------------
template<int CIN, int COUT, int MODE>
__global__ void __launch_bounds__(128) conv3x3(int inbuf, const float* __restrict__ wt,
                                               const float* __restrict__ bias, int outbuf) {
    constexpr int CCH = (CIN < 4) ? CIN : 4;
    __shared__ float tile[CCH][18][34];
    __shared__ float wsh[COUT*CIN*9];
    int tx = threadIdx.x, ty = threadIdx.y;
    int tid = ty*32 + tx;
    int w0 = blockIdx.x*32, h0 = blockIdx.y*16;

    const float* in = (MODE == 0) ? (const float*)g_image
                                  : (inbuf ? g_act1 : g_act0);
    float* out = outbuf ? g_act1 : g_act0;

    for (int i = tid; i < COUT*CIN*9; i += 128) wsh[i] = wt[i];

    float acc[4][COUT];
#pragma unroll
    for (int p = 0; p < 4; p++)
#pragma unroll
        for (int co = 0; co < COUT; co++) acc[p][co] = bias[co];

    for (int c0 = 0; c0 < CIN; c0 += CCH) {
        __syncthreads();
        for (int i = tid; i < CCH*18*34; i += 128) {
            int ci = i / (18*34); int r = i % (18*34);
            int rr = r / 34, cc = r % 34;
            int gh = h0 - 1 + rr, gw = w0 - 1 + cc;
            float v = 0.f;
            if (gh >= 0 && gh < HH && gw >= 0 && gw < WW) {
                int pix = gh*WW + gw;
                v = (MODE == 0) ? in[2*pix + (c0 + ci)] : in[(size_t)(c0 + ci)*HWSZ + pix];
            }
            tile[ci][rr][cc] = v;
        }
        __syncthreads();
#pragma unroll
        for (int ci = 0; ci < CCH; ci++) {
            float v[6][3];
#pragma unroll
            for (int rr = 0; rr < 6; rr++)
#pragma unroll
                for (int cc = 0; cc < 3; cc++)
                    v[rr][cc] = tile[ci][ty*4 + rr][tx + cc];
            for (int co = 0; co < COUT; co++) {
                const float* wp = &wsh[((co*CIN) + (c0 + ci))*9];
                float wk[9];
#pragma unroll
                for (int k = 0; k < 9; k++) wk[k] = wp[k];
#pragma unroll
                for (int p = 0; p < 4; p++)
#pragma unroll
                    for (int kh = 0; kh < 3; kh++)
#pragma unroll
                        for (int kw = 0; kw < 3; kw++)
                            acc[p][co] += wk[kh*3 + kw] * v[p + kh][kw];
            }
        }
    }

    int wcol = w0 + tx;
#pragma unroll
    for (int p = 0; p < 4; p++) {
        int hrow = h0 + ty*4 + p;
        int pix = hrow*WW + wcol;
        if (MODE == 0) {
#pragma unroll
            for (int co = 0; co < COUT; co++)
                out[(size_t)co*HWSZ + pix] = fmaxf(acc[p][co], 0.f);
        } else if (MODE == 1) {
#pragma unroll
            for (int co = 0; co < COUT; co++)
                out[(size_t)co*HWSZ + pix] = acc[p][co];
        } else {
            float2 im = g_image[pix];
            g_image[pix] = make_float2(im.x - acc[p][0], im.y - acc[p][1]);
        }
    }
}

// ---------------- batchnorm: partial stats spread over (NK x BN_CHUNKS) blocks ----
__global__ void bn_stats_part(int buf) {
    __shared__ double sh[256], sh2[256];
    const float* x = buf ? g_act1 : g_act0;
    int c = blockIdx.x, chunk = blockIdx.y, t = threadIdx.x;
    const int CH = HWSZ / BN_CHUNKS;
    const float* p = x + (size_t)c*HWSZ + (size_t)chunk*CH;
    double s = 0.0, s2 = 0.0;
    for (int i = t; i < CH; i += 256) {
        float v = p[i];
        s += v; s2 += (double)v*(double)v;
    }
    sh[t] = s; sh2[t] = s2; __syncthreads();
    for (int o = 128; o > 0; o >>= 1) {
        if (t < o) { sh[t] += sh[t + o]; sh2[t] += sh2[t + o]; }
        __syncthreads();
    }
    if (t == 0) g_bnpart[c*BN_CHUNKS + chunk] = make_double2(sh[0], sh2[0]);
}

__global__ void bn_finalize(const float* __restrict__ g, const float* __restrict__ be) {
    int c = threadIdx.x;
    if (c >= NK) return;
    double s = 0.0, s2 = 0.0;
#pragma unroll
    for (int k = 0; k < BN_CHUNKS; k++) {
        double2 v = g_bnpart[c*BN_CHUNKS + k];
        s += v.x; s2 += v.y;
    }
    double m = s * (1.0 / HWSZ);
    double var = s2 * (1.0 / HWSZ) - m*m;
    float sc = g[c] * rsqrtf((float)var + 1e-5f);
    g_bnscale[c] = sc;
    g_bnshift[c] = be[c] - (float)m * sc;
}

__global__ void bn_apply(int buf) {
    float* x = buf ? g_act1 : g_act0;
    int idx = blockIdx.x*256 + threadIdx.x;
    if (idx >= NK*HWSZ) return;
    int c = idx / HWSZ;
    float v = x[idx];
    x[idx] = fmaxf(v*g_bnscale[c] + g_bnshift[c], 0.f);
}

// ---------------- CG pointwise ----------------
__global__ void cg_dq(const float* __restrict__ scale_layers, int it) {
    int t = blockIdx.x*blockDim.x + threadIdx.x;
    if (t >= HWSZ) return;
    float lam = scale_layers[it];
    float wl = g_wsum[t] + lam;
    float2 im = g_image[t], ahb = g_Ahb[t];
    float2 d = make_float2(ahb.x - wl*im.x, ahb.y - wl*im.y);
    g_d[t] = d;
    g_Qd[t] = make_float2(wl*d.x, wl*d.y);
}

// ---------------- Gram: M1 = D^H D, M2 = D^H Qd ----------------
__global__ void gram_kernel() {
    __shared__ float2 sDi[16][17], sDj[16][17], sQj[16][17];
    int tx = threadIdx.x, ty = threadIdx.y;
    int i = blockIdx.y*16 + ty, j = blockIdx.x*16 + tx;
    float2 a1 = make_float2(0.f, 0.f), a2 = make_float2(0.f, 0.f);
    for (int h0 = 0; h0 < HH; h0 += 16) {
        sDi[ty][tx] = g_d[(h0 + ty)*WW + blockIdx.y*16 + tx];
        sDj[ty][tx] = g_d[(h0 + ty)*WW + blockIdx.x*16 + tx];
        sQj[ty][tx] = g_Qd[(h0 + ty)*WW + blockIdx.x*16 + tx];
        __syncthreads();
#pragma unroll
        for (int hh = 0; hh < 16; hh++) {
            float2 a = sDi[hh][ty];
            float2 b = sDj[hh][tx];
            float2 q = sQj[hh][tx];
            a1.x += a.x*b.x + a.y*b.y; a1.y += a.x*b.y - a.y*b.x;
            a2.x += a.x*q.x + a.y*q.y; a2.y += a.x*q.y - a.y*q.x;
        }
        __syncthreads();
    }
    g_M1[i*WW + j] = a1;
    g_M2[i*WW + j] = a2;
}

// ---------------- alpha: fp32 Smith-scaled complex division, 2-stage reduce ----
// Smith's algorithm keeps all intermediates ~|M| (~1e35 max) — no fp64 needed,
// no overflow. Fixed partitioning => deterministic.
__global__ void alpha_part() {
    __shared__ float sr[256], si[256];
    int t = threadIdx.x;
    int k = blockIdx.x*256 + t;
    float2 m1 = g_M1[k], m2 = g_M2[k];
    float ar, ai;
    if (fabsf(m2.x) >= fabsf(m2.y)) {
        float r = m2.y / m2.x;
        float den = m2.x + m2.y*r;
        ar = (m1.x + m1.y*r) / den;
        ai = (m1.y - m1.x*r) / den;
    } else {
        float r = m2.x / m2.y;
        float den = m2.y + m2.x*r;
        ar = (m1.x*r + m1.y) / den;
        ai = (m1.y*r - m1.x) / den;
    }
    sr[t] = ar; si[t] = ai; __syncthreads();
    for (int o = 128; o > 0; o >>= 1) {
        if (t < o) { sr[t] += sr[t + o]; si[t] += si[t + o]; }
        __syncthreads();
    }
    if (t == 0) g_apart[blockIdx.x] = make_float2(sr[0], si[0]);
}

__global__ void alpha_final() {
    __shared__ float sr[1024], si[1024];
    int t = threadIdx.x; // 1024
    float ar = 0.f, ai = 0.f;
    if (t < ALPHA_BLKS) { float2 v = g_apart[t]; ar = v.x; ai = v.y; }
    sr[t] = ar; si[t] = ai; __syncthreads();
    for (int o = 512; o > 0; o >>= 1) {
        if (t < o) { sr[t] += sr[t + o]; si[t] += si[t + o]; }
        __syncthreads();
    }
    if (t == 0) g_alpha = make_float2(sr[0], si[0]);
}

// ---------------- image += alpha * d ----------------
__global__ void update_kernel() {
    int t = blockIdx.x*blockDim.x + threadIdx.x;
    if (t >= HWSZ) return;
    float2 al = g_alpha;
    float2 d = g_d[t], im = g_image[t];
    im.x += al.x*d.x - al.y*d.y;
    im.y += al.x*d.y + al.y*d.x;
    g_image[t] = im;
}

// ---------------- crop ----------------
__global__ void crop_kernel(float2* __restrict__ out) {
    int t = blockIdx.x*blockDim.x + threadIdx.x;
    if (t >= WW*WW) return;
    int r = t / WW, c = t % WW;
    out[t] = g_image[(r + 64)*WW + c];
}

// ---------------- launch ----------------
extern "C" void kernel_launch(void* const* d_in, const int* in_sizes, int n_in,
                              void* d_out, int out_size) {
    (void)in_sizes; (void)n_in; (void)out_size;
    const float2* b_in  = (const float2*)d_in[0];
    const float2* smaps = (const float2*)d_in[1];
    const float* w0  = (const float*)d_in[2];
    const float* b0  = (const float*)d_in[3];
    const float* w1  = (const float*)d_in[4];
    const float* b1  = (const float*)d_in[5];
    const float* g1  = (const float*)d_in[6];
    const float* be1 = (const float*)d_in[7];
    const float* w2  = (const float*)d_in[8];
    const float* b2  = (const float*)d_in[9];
    const float* g2  = (const float*)d_in[10];
    const float* be2 = (const float*)d_in[11];
    const float* wl  = (const float*)d_in[12];
    const float* bl  = (const float*)d_in[13];
    const float* scl = (const float*)d_in[14];

    const int PW = (HWSZ + 255) / 256;

    ifft_col512<<<dim3(WW, CC), 256>>>(b_in);
    ifft_row384<<<dim3(HH, CC), 128>>>();
    decode_kernel<<<PW, 256>>>(smaps);

    dim3 cgrid(WW/32, HH/16), cblk(32, 4);
    for (int it = 0; it < NITER; it++) {
        conv3x3<2, 16, 0><<<cgrid, cblk>>>(0, w0, b0, 0);
        conv3x3<16, 16, 1><<<cgrid, cblk>>>(0, w1, b1, 1);
        bn_stats_part<<<dim3(NK, BN_CHUNKS), 256>>>(1);
        bn_finalize<<<1, 32>>>(g1, be1);
        bn_apply<<<(NK*HWSZ + 255)/256, 256>>>(1);
        conv3x3<16, 16, 1><<<cgrid, cblk>>>(1, w2, b2, 0);
        bn_stats_part<<<dim3(NK, BN_CHUNKS), 256>>>(0);
        bn_finalize<<<1, 32>>>(g2, be2);
        bn_apply<<<(NK*HWSZ + 255)/256, 256>>>(0);
        conv3x3<16, 2, 2><<<cgrid, cblk>>>(0, wl, bl, 0);
        cg_dq<<<PW, 256>>>(scl, it);
        gram_kernel<<<dim3(WW/16, WW/16), dim3(16, 16)>>>();
        alpha_part<<<ALPHA_BLKS, 256>>>();
        alpha_final<<<1, 1024>>>();
        update_kernel<<<PW, 256>>>();
    }
    crop_kernel<<<(WW*WW + 255)/256, 256>>>((float2*)d_out);
}

// round 13
// speedup vs baseline: 6.7307x; 2.0242x over previous
#include <cuda_runtime.h>

#define CC 16
#define HH 512
#define WW 384
#define HWSZ (HH*WW)
#define NK 16
#define NITER 4
#define BN_CHUNKS 8
#define ALPHA_BLKS 576   // 576*256 == WW*WW exactly
#define GRAM_SPLIT 2

// ---------------- device scratch (static, no allocation) ----------------
__device__ float2 g_kbuf[CC*HWSZ];
__device__ float2 g_image[HWSZ];
__device__ float2 g_Ahb[HWSZ];
__device__ float2 g_d[HWSZ];
__device__ float2 g_Qd[HWSZ];
__device__ float  g_wsum[HWSZ];
__device__ float  g_act0[NK*HWSZ];
__device__ float  g_act1[NK*HWSZ];
__device__ float2 g_M1s[GRAM_SPLIT][WW*WW];
__device__ float2 g_M2s[GRAM_SPLIT][WW*WW];
__device__ double2 g_bnpart[NK*BN_CHUNKS];
__device__ float2 g_apart[ALPHA_BLKS];

__device__ __forceinline__ float2 cmulf(float2 a, float2 b) {
    return make_float2(a.x*b.x - a.y*b.y, a.x*b.y + a.y*b.x);
}

// ---------------- inverse FFT, column direction, N=512 ----------------
__global__ void ifft_col512(const float2* __restrict__ in) {
    __shared__ float2 s[512];
    int col = blockIdx.x, coil = blockIdx.y;
    const float2* p = in + (size_t)coil*HWSZ;
    float2* q = g_kbuf + (size_t)coil*HWSZ;
    int t = threadIdx.x; // 256
    for (int k = t; k < 512; k += 256) {
        int br = __brev((unsigned)k) >> 23;
        s[br] = p[(size_t)k*WW + col];
    }
    __syncthreads();
    int lh = 0;
    for (int len = 2; len <= 512; len <<= 1, lh++) {
        int half = len >> 1;
        int j = t & (half - 1);
        int i0 = ((t >> lh) << (lh + 1)) + j;
        int i1 = i0 + half;
        float ang = 6.28318530717958647692f * (float)j / (float)len;
        float sn, cs; sincosf(ang, &sn, &cs);
        float2 u = s[i0], v = s[i1];
        float2 vw = make_float2(v.x*cs - v.y*sn, v.x*sn + v.y*cs);
        s[i0] = make_float2(u.x + vw.x, u.y + vw.y);
        s[i1] = make_float2(u.x - vw.x, u.y - vw.y);
        __syncthreads();
    }
    const float sc = 0.04419417382415922f; // 1/sqrt(512)
    for (int k = t; k < 512; k += 256) {
        float2 v = s[k];
        q[(size_t)k*WW + col] = make_float2(v.x*sc, v.y*sc);
    }
}

// ---------------- inverse FFT, row direction, N=384 = 3 * 128 ----------------
__global__ void ifft_row384() {
    __shared__ float2 f[3][128];
    int row = blockIdx.x, coil = blockIdx.y;
    float2* p = g_kbuf + (size_t)coil*HWSZ + (size_t)row*WW;
    int t = threadIdx.x; // 128
    int br = __brev((unsigned)t) >> 25;
    f[0][br] = p[3*t + 0];
    f[1][br] = p[3*t + 1];
    f[2][br] = p[3*t + 2];
    __syncthreads();
    int lh = 0;
    for (int len = 2; len <= 128; len <<= 1, lh++) {
        int half = len >> 1;
        for (int bt = t; bt < 192; bt += 128) {
            int sub = bt >> 6;
            int u = bt & 63;
            int j = u & (half - 1);
            int i0 = ((u >> lh) << (lh + 1)) + j;
            float ang = 6.28318530717958647692f * (float)j / (float)len;
            float sn, cs; sincosf(ang, &sn, &cs);
            float2 a = f[sub][i0], b = f[sub][i0 + half];
            float2 bw = make_float2(b.x*cs - b.y*sn, b.x*sn + b.y*cs);
            f[sub][i0] = make_float2(a.x + bw.x, a.y + bw.y);
            f[sub][i0 + half] = make_float2(a.x - bw.x, a.y - bw.y);
        }
        __syncthreads();
    }
    float ang1 = 6.28318530717958647692f * (float)t / 384.0f;
    float sn1, cs1; sincosf(ang1, &sn1, &cs1);
    float sn2, cs2; sincosf(2.0f*ang1, &sn2, &cs2);
    float2 t0 = f[0][t];
    float2 t1 = cmulf(f[1][t], make_float2(cs1, sn1));
    float2 t2 = cmulf(f[2][t], make_float2(cs2, sn2));
    const float h3 = 0.86602540378443864676f;
    float2 w3  = make_float2(-0.5f,  h3);
    float2 w3b = make_float2(-0.5f, -h3);
    const float sc = 0.05103103630798288f; // 1/sqrt(384)
    float2 a1 = cmulf(w3, t1),  a2 = cmulf(w3b, t2);
    float2 b1 = cmulf(w3b, t1), b2 = cmulf(w3,  t2);
    float2 X0 = make_float2(t0.x + t1.x + t2.x, t0.y + t1.y + t2.y);
    float2 X1 = make_float2(t0.x + a1.x + a2.x, t0.y + a1.y + a2.y);
    float2 X2 = make_float2(t0.x + b1.x + b2.x, t0.y + b1.y + b2.y);
    p[t]       = make_float2(X0.x*sc, X0.y*sc);
    p[128 + t] = make_float2(X1.x*sc, X1.y*sc);
    p[256 + t] = make_float2(X2.x*sc, X2.y*sc);
}

// ---------------- decode ----------------
__global__ void decode_kernel(const float2* __restrict__ smaps) {
    int t = blockIdx.x*blockDim.x + threadIdx.x;
    if (t >= HWSZ) return;
    float2 acc = make_float2(0.f, 0.f);
    float ws = 0.f;
#pragma unroll
    for (int c = 0; c < CC; c++) {
        float2 s = smaps[(size_t)c*HWSZ + t];
        float2 k = g_kbuf[(size_t)c*HWSZ + t];
        acc.x += s.x*k.x + s.y*k.y;
        acc.y += s.x*k.y - s.y*k.x;
        ws += s.x*s.x + s.y*s.y;
    }
    g_image[t] = acc;
    g_Ahb[t]   = acc;
    g_wsum[t]  = ws;
}

// ---------------- conv 3x3 SAME, register-blocked, fully unrolled ----------------
// Weights are repacked into shared with stride 12 (16B-aligned) so each wk[9]
// is 3x LDS.128. Accumulators fully register-resident (co loop unrolled).
template<int CIN, int COUT, int MODE>
__global__ void __launch_bounds__(128) conv3x3(int inbuf, const float* __restrict__ wt,
                                               const float* __restrict__ bias, int outbuf) {
    constexpr int CCH = (CIN < 4) ? CIN : 4;
    __shared__ float tile[CCH][18][34];
    __shared__ float4 wsh4[COUT*CIN*3];
    float* wsh = (float*)wsh4;
    int tx = threadIdx.x, ty = threadIdx.y;
    int tid = ty*32 + tx;
    int w0 = blockIdx.x*32, h0 = blockIdx.y*16;

    const float* in = (MODE == 0) ? (const float*)g_image
                                  : (inbuf ? g_act1 : g_act0);
    float* out = outbuf ? g_act1 : g_act0;

    // repack weights [idx][9] -> [idx][12]
    for (int i = tid; i < COUT*CIN; i += 128) {
#pragma unroll
        for (int k = 0; k < 9; k++) wsh[i*12 + k] = wt[i*9 + k];
#pragma unroll
        for (int k = 9; k < 12; k++) wsh[i*12 + k] = 0.f;
    }

    float acc[4][COUT];
#pragma unroll
    for (int p = 0; p < 4; p++)
#pragma unroll
        for (int co = 0; co < COUT; co++) acc[p][co] = bias[co];

    for (int c0 = 0; c0 < CIN; c0 += CCH) {
        __syncthreads();
        for (int i = tid; i < CCH*18*34; i += 128) {
            int ci = i / (18*34); int r = i % (18*34);
            int rr = r / 34, cc = r % 34;
            int gh = h0 - 1 + rr, gw = w0 - 1 + cc;
            float v = 0.f;
            if (gh >= 0 && gh < HH && gw >= 0 && gw < WW) {
                int pix = gh*WW + gw;
                v = (MODE == 0) ? in[2*pix + (c0 + ci)] : in[(size_t)(c0 + ci)*HWSZ + pix];
            }
            tile[ci][rr][cc] = v;
        }
        __syncthreads();
#pragma unroll
        for (int ci = 0; ci < CCH; ci++) {
            float v[6][3];
#pragma unroll
            for (int rr = 0; rr < 6; rr++)
#pragma unroll
                for (int cc = 0; cc < 3; cc++)
                    v[rr][cc] = tile[ci][ty*4 + rr][tx + cc];
#pragma unroll
            for (int co = 0; co < COUT; co++) {
                const float4* wp = &wsh4[((co*CIN) + (c0 + ci))*3];
                float4 wa = wp[0], wb = wp[1], wc = wp[2];
                float wk[9] = {wa.x, wa.y, wa.z, wa.w, wb.x, wb.y, wb.z, wb.w, wc.x};
#pragma unroll
                for (int p = 0; p < 4; p++)
#pragma unroll
                    for (int kh = 0; kh < 3; kh++)
#pragma unroll
                        for (int kw = 0; kw < 3; kw++)
                            acc[p][co] += wk[kh*3 + kw] * v[p + kh][kw];
            }
        }
    }

    int wcol = w0 + tx;
#pragma unroll
    for (int p = 0; p < 4; p++) {
        int hrow = h0 + ty*4 + p;
        int pix = hrow*WW + wcol;
        if (MODE == 0) {
#pragma unroll
            for (int co = 0; co < COUT; co++)
                out[(size_t)co*HWSZ + pix] = fmaxf(acc[p][co], 0.f);
        } else if (MODE == 1) {
#pragma unroll
            for (int co = 0; co < COUT; co++)
                out[(size_t)co*HWSZ + pix] = acc[p][co];
        } else {
            float2 im = g_image[pix];
            g_image[pix] = make_float2(im.x - acc[p][0], im.y - acc[p][1]);
        }
    }
}

// ---------------- batchnorm: partial stats spread over (NK x BN_CHUNKS) blocks ----
__global__ void bn_stats_part(int buf) {
    __shared__ double sh[256], sh2[256];
    const float* x = buf ? g_act1 : g_act0;
    int c = blockIdx.x, chunk = blockIdx.y, t = threadIdx.x;
    const int CH = HWSZ / BN_CHUNKS;
    const float* p = x + (size_t)c*HWSZ + (size_t)chunk*CH;
    double s = 0.0, s2 = 0.0;
    for (int i = t; i < CH; i += 256) {
        float v = p[i];
        s += v; s2 += (double)v*(double)v;
    }
    sh[t] = s; sh2[t] = s2; __syncthreads();
    for (int o = 128; o > 0; o >>= 1) {
        if (t < o) { sh[t] += sh[t + o]; sh2[t] += sh2[t + o]; }
        __syncthreads();
    }
    if (t == 0) g_bnpart[c*BN_CHUNKS + chunk] = make_double2(sh[0], sh2[0]);
}

// bn finalize fused into apply: each 256-elem block lies inside one channel
__global__ void bn_apply(int buf, const float* __restrict__ g, const float* __restrict__ be) {
    __shared__ float s_sc, s_sh;
    float* x = buf ? g_act1 : g_act0;
    int idx = blockIdx.x*256 + threadIdx.x;
    int c = (blockIdx.x*256) / HWSZ;
    if (threadIdx.x == 0) {
        double s = 0.0, s2 = 0.0;
#pragma unroll
        for (int k = 0; k < BN_CHUNKS; k++) {
            double2 v = g_bnpart[c*BN_CHUNKS + k];
            s += v.x; s2 += v.y;
        }
        double m = s * (1.0 / HWSZ);
        double var = s2 * (1.0 / HWSZ) - m*m;
        float sc = g[c] * rsqrtf((float)var + 1e-5f);
        s_sc = sc;
        s_sh = be[c] - (float)m * sc;
    }
    __syncthreads();
    float v = x[idx];
    x[idx] = fmaxf(v*s_sc + s_sh, 0.f);
}

// ---------------- CG pointwise ----------------
__global__ void cg_dq(const float* __restrict__ scale_layers, int it) {
    int t = blockIdx.x*blockDim.x + threadIdx.x;
    if (t >= HWSZ) return;
    float lam = scale_layers[it];
    float wl = g_wsum[t] + lam;
    float2 im = g_image[t], ahb = g_Ahb[t];
    float2 d = make_float2(ahb.x - wl*im.x, ahb.y - wl*im.y);
    g_d[t] = d;
    g_Qd[t] = make_float2(wl*d.x, wl*d.y);
}

// ---------------- Gram: M1 = D^H D, M2 = D^H Qd, 2x2 reg tile + K-split ----------
__global__ void __launch_bounds__(256) gram_kernel() {
    __shared__ float2 sDi[16][33], sDj[16][33], sQj[16][33];
    int tx = threadIdx.x, ty = threadIdx.y; // 16x16
    int i0 = blockIdx.y*32, j0 = blockIdx.x*32;
    int hbase = blockIdx.z * (HH / GRAM_SPLIT);
    float2 m1[2][2], m2[2][2];
#pragma unroll
    for (int a = 0; a < 2; a++)
#pragma unroll
        for (int b = 0; b < 2; b++) {
            m1[a][b] = make_float2(0.f, 0.f);
            m2[a][b] = make_float2(0.f, 0.f);
        }
    for (int h0 = hbase; h0 < hbase + HH/GRAM_SPLIT; h0 += 16) {
        sDi[ty][tx]      = g_d [(h0 + ty)*WW + i0 + tx];
        sDi[ty][tx + 16] = g_d [(h0 + ty)*WW + i0 + tx + 16];
        sDj[ty][tx]      = g_d [(h0 + ty)*WW + j0 + tx];
        sDj[ty][tx + 16] = g_d [(h0 + ty)*WW + j0 + tx + 16];
        sQj[ty][tx]      = g_Qd[(h0 + ty)*WW + j0 + tx];
        sQj[ty][tx + 16] = g_Qd[(h0 + ty)*WW + j0 + tx + 16];
        __syncthreads();
#pragma unroll
        for (int hh = 0; hh < 16; hh++) {
            float2 a0 = sDi[hh][2*ty], a1 = sDi[hh][2*ty + 1];
            float2 b0 = sDj[hh][2*tx], b1 = sDj[hh][2*tx + 1];
            float2 q0 = sQj[hh][2*tx], q1 = sQj[hh][2*tx + 1];
#pragma unroll
            for (int a = 0; a < 2; a++) {
                float2 av = a ? a1 : a0;
#pragma unroll
                for (int b = 0; b < 2; b++) {
                    float2 bv = b ? b1 : b0;
                    float2 qv = b ? q1 : q0;
                    m1[a][b].x += av.x*bv.x + av.y*bv.y;
                    m1[a][b].y += av.x*bv.y - av.y*bv.x;
                    m2[a][b].x += av.x*qv.x + av.y*qv.y;
                    m2[a][b].y += av.x*qv.y - av.y*qv.x;
                }
            }
        }
        __syncthreads();
    }
    int z = blockIdx.z;
#pragma unroll
    for (int a = 0; a < 2; a++)
#pragma unroll
        for (int b = 0; b < 2; b++) {
            int i = i0 + 2*ty + a, j = j0 + 2*tx + b;
            g_M1s[z][i*WW + j] = m1[a][b];
            g_M2s[z][i*WW + j] = m2[a][b];
        }
}

// ---------------- alpha partials: combine K-splits + Smith-scaled divide ----------
__global__ void alpha_part() {
    __shared__ float sr[256], si[256];
    int t = threadIdx.x;
    int k = blockIdx.x*256 + t;
    float2 p0 = g_M1s[0][k], p1 = g_M1s[1][k];
    float2 q0 = g_M2s[0][k], q1 = g_M2s[1][k];
    float2 m1 = make_float2(p0.x + p1.x, p0.y + p1.y);
    float2 m2 = make_float2(q0.x + q1.x, q0.y + q1.y);
    float ar, ai;
    if (fabsf(m2.x) >= fabsf(m2.y)) {
        float r = m2.y / m2.x;
        float den = m2.x + m2.y*r;
        ar = (m1.x + m1.y*r) / den;
        ai = (m1.y - m1.x*r) / den;
    } else {
        float r = m2.x / m2.y;
        float den = m2.y + m2.x*r;
        ar = (m1.x*r + m1.y) / den;
        ai = (m1.y*r - m1.x) / den;
    }
    sr[t] = ar; si[t] = ai; __syncthreads();
    for (int o = 128; o > 0; o >>= 1) {
        if (t < o) { sr[t] += sr[t + o]; si[t] += si[t + o]; }
        __syncthreads();
    }
    if (t == 0) g_apart[blockIdx.x] = make_float2(sr[0], si[0]);
}

// ---------------- image += alpha * d  (alpha reduced in-block from partials) ----
__global__ void update_kernel() {
    __shared__ float sr[256], si[256];
    int t = threadIdx.x;
    float ar = 0.f, ai = 0.f;
    for (int k = t; k < ALPHA_BLKS; k += 256) {
        float2 v = g_apart[k];
        ar += v.x; ai += v.y;
    }
    sr[t] = ar; si[t] = ai; __syncthreads();
    for (int o = 128; o > 0; o >>= 1) {
        if (t < o) { sr[t] += sr[t + o]; si[t] += si[t + o]; }
        __syncthreads();
    }
    float alx = sr[0], aly = si[0];
    int idx = blockIdx.x*256 + t;
    if (idx >= HWSZ) return;
    float2 d = g_d[idx], im = g_image[idx];
    im.x += alx*d.x - aly*d.y;
    im.y += alx*d.y + aly*d.x;
    g_image[idx] = im;
}

// ---------------- crop ----------------
__global__ void crop_kernel(float2* __restrict__ out) {
    int t = blockIdx.x*blockDim.x + threadIdx.x;
    if (t >= WW*WW) return;
    int r = t / WW, c = t % WW;
    out[t] = g_image[(r + 64)*WW + c];
}

// ---------------- launch ----------------
extern "C" void kernel_launch(void* const* d_in, const int* in_sizes, int n_in,
                              void* d_out, int out_size) {
    (void)in_sizes; (void)n_in; (void)out_size;
    const float2* b_in  = (const float2*)d_in[0];
    const float2* smaps = (const float2*)d_in[1];
    const float* w0  = (const float*)d_in[2];
    const float* b0  = (const float*)d_in[3];
    const float* w1  = (const float*)d_in[4];
    const float* b1  = (const float*)d_in[5];
    const float* g1  = (const float*)d_in[6];
    const float* be1 = (const float*)d_in[7];
    const float* w2  = (const float*)d_in[8];
    const float* b2  = (const float*)d_in[9];
    const float* g2  = (const float*)d_in[10];
    const float* be2 = (const float*)d_in[11];
    const float* wl  = (const float*)d_in[12];
    const float* bl  = (const float*)d_in[13];
    const float* scl = (const float*)d_in[14];

    const int PW = (HWSZ + 255) / 256;

    ifft_col512<<<dim3(WW, CC), 256>>>(b_in);
    ifft_row384<<<dim3(HH, CC), 128>>>();
    decode_kernel<<<PW, 256>>>(smaps);

    dim3 cgrid(WW/32, HH/16), cblk(32, 4);
    for (int it = 0; it < NITER; it++) {
        conv3x3<2, 16, 0><<<cgrid, cblk>>>(0, w0, b0, 0);
        conv3x3<16, 16, 1><<<cgrid, cblk>>>(0, w1, b1, 1);
        bn_stats_part<<<dim3(NK, BN_CHUNKS), 256>>>(1);
        bn_apply<<<(NK*HWSZ)/256, 256>>>(1, g1, be1);
        conv3x3<16, 16, 1><<<cgrid, cblk>>>(1, w2, b2, 0);
        bn_stats_part<<<dim3(NK, BN_CHUNKS), 256>>>(0);
        bn_apply<<<(NK*HWSZ)/256, 256>>>(0, g2, be2);
        conv3x3<16, 2, 2><<<cgrid, cblk>>>(0, wl, bl, 0);
        cg_dq<<<PW, 256>>>(scl, it);
        gram_kernel<<<dim3(WW/32, WW/32, GRAM_SPLIT), dim3(16, 16)>>>();
        alpha_part<<<ALPHA_BLKS, 256>>>();
        update_kernel<<<PW, 256>>>();
    }
    crop_kernel<<<(WW*WW + 255)/256, 256>>>((float2*)d_out);
}

// round 14
// speedup vs baseline: 7.4083x; 1.1007x over previous
#include <cuda_runtime.h>

#define CC 16
#define HH 512
#define WW 384
#define HWSZ (HH*WW)
#define NK 16
#define NITER 4
#define BN_CHUNKS 8
#define ALPHA_BLKS 576   // 576*256 == WW*WW exactly
#define GRAM_SPLIT 4

// ---------------- device scratch (static, no allocation) ----------------
__device__ float2 g_kbuf[CC*HWSZ];
__device__ float2 g_image[HWSZ];
__device__ float2 g_Ahb[HWSZ];
__device__ float2 g_d[HWSZ];
__device__ float2 g_Qd[HWSZ];
__device__ float  g_wsum[HWSZ];
__device__ float  g_act0[NK*HWSZ];
__device__ float  g_act1[NK*HWSZ];
__device__ float2 g_M1s[GRAM_SPLIT][WW*WW];
__device__ float2 g_M2s[GRAM_SPLIT][WW*WW];
__device__ double2 g_bnpart[NK*BN_CHUNKS];
__device__ float2 g_apart[ALPHA_BLKS];

__device__ __forceinline__ float2 cmulf(float2 a, float2 b) {
    return make_float2(a.x*b.x - a.y*b.y, a.x*b.y + a.y*b.x);
}

// ---------------- inverse FFT, column direction, N=512 ----------------
__global__ void ifft_col512(const float2* __restrict__ in) {
    __shared__ float2 s[512];
    int col = blockIdx.x, coil = blockIdx.y;
    const float2* p = in + (size_t)coil*HWSZ;
    float2* q = g_kbuf + (size_t)coil*HWSZ;
    int t = threadIdx.x; // 256
    for (int k = t; k < 512; k += 256) {
        int br = __brev((unsigned)k) >> 23;
        s[br] = p[(size_t)k*WW + col];
    }
    __syncthreads();
    int lh = 0;
    for (int len = 2; len <= 512; len <<= 1, lh++) {
        int half = len >> 1;
        int j = t & (half - 1);
        int i0 = ((t >> lh) << (lh + 1)) + j;
        int i1 = i0 + half;
        float ang = 6.28318530717958647692f * (float)j / (float)len;
        float sn, cs; sincosf(ang, &sn, &cs);
        float2 u = s[i0], v = s[i1];
        float2 vw = make_float2(v.x*cs - v.y*sn, v.x*sn + v.y*cs);
        s[i0] = make_float2(u.x + vw.x, u.y + vw.y);
        s[i1] = make_float2(u.x - vw.x, u.y - vw.y);
        __syncthreads();
    }
    const float sc = 0.04419417382415922f; // 1/sqrt(512)
    for (int k = t; k < 512; k += 256) {
        float2 v = s[k];
        q[(size_t)k*WW + col] = make_float2(v.x*sc, v.y*sc);
    }
}

// ---------------- inverse FFT, row direction, N=384 = 3 * 128 ----------------
__global__ void ifft_row384() {
    __shared__ float2 f[3][128];
    int row = blockIdx.x, coil = blockIdx.y;
    float2* p = g_kbuf + (size_t)coil*HWSZ + (size_t)row*WW;
    int t = threadIdx.x; // 128
    int br = __brev((unsigned)t) >> 25;
    f[0][br] = p[3*t + 0];
    f[1][br] = p[3*t + 1];
    f[2][br] = p[3*t + 2];
    __syncthreads();
    int lh = 0;
    for (int len = 2; len <= 128; len <<= 1, lh++) {
        int half = len >> 1;
        for (int bt = t; bt < 192; bt += 128) {
            int sub = bt >> 6;
            int u = bt & 63;
            int j = u & (half - 1);
            int i0 = ((u >> lh) << (lh + 1)) + j;
            float ang = 6.28318530717958647692f * (float)j / (float)len;
            float sn, cs; sincosf(ang, &sn, &cs);
            float2 a = f[sub][i0], b = f[sub][i0 + half];
            float2 bw = make_float2(b.x*cs - b.y*sn, b.x*sn + b.y*cs);
            f[sub][i0] = make_float2(a.x + bw.x, a.y + bw.y);
            f[sub][i0 + half] = make_float2(a.x - bw.x, a.y - bw.y);
        }
        __syncthreads();
    }
    float ang1 = 6.28318530717958647692f * (float)t / 384.0f;
    float sn1, cs1; sincosf(ang1, &sn1, &cs1);
    float sn2, cs2; sincosf(2.0f*ang1, &sn2, &cs2);
    float2 t0 = f[0][t];
    float2 t1 = cmulf(f[1][t], make_float2(cs1, sn1));
    float2 t2 = cmulf(f[2][t], make_float2(cs2, sn2));
    const float h3 = 0.86602540378443864676f;
    float2 w3  = make_float2(-0.5f,  h3);
    float2 w3b = make_float2(-0.5f, -h3);
    const float sc = 0.05103103630798288f; // 1/sqrt(384)
    float2 a1 = cmulf(w3, t1),  a2 = cmulf(w3b, t2);
    float2 b1 = cmulf(w3b, t1), b2 = cmulf(w3,  t2);
    float2 X0 = make_float2(t0.x + t1.x + t2.x, t0.y + t1.y + t2.y);
    float2 X1 = make_float2(t0.x + a1.x + a2.x, t0.y + a1.y + a2.y);
    float2 X2 = make_float2(t0.x + b1.x + b2.x, t0.y + b1.y + b2.y);
    p[t]       = make_float2(X0.x*sc, X0.y*sc);
    p[128 + t] = make_float2(X1.x*sc, X1.y*sc);
    p[256 + t] = make_float2(X2.x*sc, X2.y*sc);
}

// ---------------- decode ----------------
__global__ void decode_kernel(const float2* __restrict__ smaps) {
    int t = blockIdx.x*blockDim.x + threadIdx.x;
    if (t >= HWSZ) return;
    float2 acc = make_float2(0.f, 0.f);
    float ws = 0.f;
#pragma unroll
    for (int c = 0; c < CC; c++) {
        float2 s = smaps[(size_t)c*HWSZ + t];
        float2 k = g_kbuf[(size_t)c*HWSZ + t];
        acc.x += s.x*k.x + s.y*k.y;
        acc.y += s.x*k.y - s.y*k.x;
        ws += s.x*s.x + s.y*s.y;
    }
    g_image[t] = acc;
    g_Ahb[t]   = acc;
    g_wsum[t]  = ws;
}

// ---------------- conv 3x3 SAME, register-blocked, fully unrolled ----------------
// MODE 0: image (interleaved 2ch) -> relu(conv) planar
// MODE 1: planar -> planar raw (pre-BN)
// MODE 2: planar -> residual update of image, FUSED with cg_dq (emits d, Qd)
// BNIN 1: apply batchnorm(scale/shift from g_bnpart)+relu to input at tile load.
//         Per-block scale/shift recomputed from the same double sums (identical math).
template<int CIN, int COUT, int MODE, int BNIN>
__global__ void __launch_bounds__(128) conv3x3(int inbuf, const float* __restrict__ wt,
                                               const float* __restrict__ bias, int outbuf,
                                               const float* __restrict__ bng,
                                               const float* __restrict__ bnbe,
                                               const float* __restrict__ scl, int it) {
    constexpr int CCH = (CIN < 4) ? CIN : 4;
    __shared__ float tile[CCH][18][34];
    __shared__ float4 wsh4[COUT*CIN*3];
    __shared__ float bnsc[CIN], bnsh[CIN];
    float* wsh = (float*)wsh4;
    int tx = threadIdx.x, ty = threadIdx.y;
    int tid = ty*32 + tx;
    int w0 = blockIdx.x*32, h0 = blockIdx.y*16;

    const float* in = (MODE == 0) ? (const float*)g_image
                                  : (inbuf ? g_act1 : g_act0);
    float* out = outbuf ? g_act1 : g_act0;

    // repack weights [idx][9] -> [idx][12]
    for (int i = tid; i < COUT*CIN; i += 128) {
#pragma unroll
        for (int k = 0; k < 9; k++) wsh[i*12 + k] = wt[i*9 + k];
#pragma unroll
        for (int k = 9; k < 12; k++) wsh[i*12 + k] = 0.f;
    }
    if (BNIN) {
        if (tid < CIN) {
            double s = 0.0, s2 = 0.0;
#pragma unroll
            for (int k = 0; k < BN_CHUNKS; k++) {
                double2 v = g_bnpart[tid*BN_CHUNKS + k];
                s += v.x; s2 += v.y;
            }
            double m = s * (1.0 / HWSZ);
            double var = s2 * (1.0 / HWSZ) - m*m;
            float sc = bng[tid] * rsqrtf((float)var + 1e-5f);
            bnsc[tid] = sc;
            bnsh[tid] = bnbe[tid] - (float)m * sc;
        }
    }

    float acc[4][COUT];
#pragma unroll
    for (int p = 0; p < 4; p++)
#pragma unroll
        for (int co = 0; co < COUT; co++) acc[p][co] = bias[co];

    for (int c0 = 0; c0 < CIN; c0 += CCH) {
        __syncthreads();   // also covers bnsc/bnsh + wsh writes on first pass
        for (int i = tid; i < CCH*18*34; i += 128) {
            int ci = i / (18*34); int r = i % (18*34);
            int rr = r / 34, cc = r % 34;
            int gh = h0 - 1 + rr, gw = w0 - 1 + cc;
            float v = 0.f;
            if (gh >= 0 && gh < HH && gw >= 0 && gw < WW) {
                int pix = gh*WW + gw;
                v = (MODE == 0) ? in[2*pix + (c0 + ci)] : in[(size_t)(c0 + ci)*HWSZ + pix];
                if (BNIN) v = fmaxf(v*bnsc[c0 + ci] + bnsh[c0 + ci], 0.f);
            }
            tile[ci][rr][cc] = v;
        }
        __syncthreads();
#pragma unroll
        for (int ci = 0; ci < CCH; ci++) {
            float v[6][3];
#pragma unroll
            for (int rr = 0; rr < 6; rr++)
#pragma unroll
                for (int cc = 0; cc < 3; cc++)
                    v[rr][cc] = tile[ci][ty*4 + rr][tx + cc];
#pragma unroll
            for (int co = 0; co < COUT; co++) {
                const float4* wp = &wsh4[((co*CIN) + (c0 + ci))*3];
                float4 wa = wp[0], wb = wp[1], wc = wp[2];
                float wk[9] = {wa.x, wa.y, wa.z, wa.w, wb.x, wb.y, wb.z, wb.w, wc.x};
#pragma unroll
                for (int p = 0; p < 4; p++)
#pragma unroll
                    for (int kh = 0; kh < 3; kh++)
#pragma unroll
                        for (int kw = 0; kw < 3; kw++)
                            acc[p][co] += wk[kh*3 + kw] * v[p + kh][kw];
            }
        }
    }

    float lam = (MODE == 2) ? scl[it] : 0.f;
    int wcol = w0 + tx;
#pragma unroll
    for (int p = 0; p < 4; p++) {
        int hrow = h0 + ty*4 + p;
        int pix = hrow*WW + wcol;
        if (MODE == 0) {
#pragma unroll
            for (int co = 0; co < COUT; co++)
                out[(size_t)co*HWSZ + pix] = fmaxf(acc[p][co], 0.f);
        } else if (MODE == 1) {
#pragma unroll
            for (int co = 0; co < COUT; co++)
                out[(size_t)co*HWSZ + pix] = acc[p][co];
        } else {
            // residual update + fused cg_dq
            float2 im = g_image[pix];
            im.x -= acc[p][0]; im.y -= acc[p][1];
            g_image[pix] = im;
            float wl = g_wsum[pix] + lam;
            float2 ahb = g_Ahb[pix];
            float2 d = make_float2(ahb.x - wl*im.x, ahb.y - wl*im.y);
            g_d[pix] = d;
            g_Qd[pix] = make_float2(wl*d.x, wl*d.y);
        }
    }
}

// ---------------- batchnorm: partial stats spread over (NK x BN_CHUNKS) blocks ----
__global__ void bn_stats_part(int buf) {
    __shared__ double sh[256], sh2[256];
    const float* x = buf ? g_act1 : g_act0;
    int c = blockIdx.x, chunk = blockIdx.y, t = threadIdx.x;
    const int CH = HWSZ / BN_CHUNKS;
    const float* p = x + (size_t)c*HWSZ + (size_t)chunk*CH;
    double s = 0.0, s2 = 0.0;
    for (int i = t; i < CH; i += 256) {
        float v = p[i];
        s += v; s2 += (double)v*(double)v;
    }
    sh[t] = s; sh2[t] = s2; __syncthreads();
    for (int o = 128; o > 0; o >>= 1) {
        if (t < o) { sh[t] += sh[t + o]; sh2[t] += sh2[t + o]; }
        __syncthreads();
    }
    if (t == 0) g_bnpart[c*BN_CHUNKS + chunk] = make_double2(sh[0], sh2[0]);
}

// ---------------- Gram: M1 = D^H D, M2 = D^H Qd, 2x2 reg tile + K-split ----------
__global__ void __launch_bounds__(256) gram_kernel() {
    __shared__ float2 sDi[16][33], sDj[16][33], sQj[16][33];
    int tx = threadIdx.x, ty = threadIdx.y; // 16x16
    int i0 = blockIdx.y*32, j0 = blockIdx.x*32;
    int hbase = blockIdx.z * (HH / GRAM_SPLIT);
    float2 m1[2][2], m2[2][2];
#pragma unroll
    for (int a = 0; a < 2; a++)
#pragma unroll
        for (int b = 0; b < 2; b++) {
            m1[a][b] = make_float2(0.f, 0.f);
            m2[a][b] = make_float2(0.f, 0.f);
        }
    for (int h0 = hbase; h0 < hbase + HH/GRAM_SPLIT; h0 += 16) {
        sDi[ty][tx]      = g_d [(h0 + ty)*WW + i0 + tx];
        sDi[ty][tx + 16] = g_d [(h0 + ty)*WW + i0 + tx + 16];
        sDj[ty][tx]      = g_d [(h0 + ty)*WW + j0 + tx];
        sDj[ty][tx + 16] = g_d [(h0 + ty)*WW + j0 + tx + 16];
        sQj[ty][tx]      = g_Qd[(h0 + ty)*WW + j0 + tx];
        sQj[ty][tx + 16] = g_Qd[(h0 + ty)*WW + j0 + tx + 16];
        __syncthreads();
#pragma unroll
        for (int hh = 0; hh < 16; hh++) {
            float2 a0 = sDi[hh][2*ty], a1 = sDi[hh][2*ty + 1];
            float2 b0 = sDj[hh][2*tx], b1 = sDj[hh][2*tx + 1];
            float2 q0 = sQj[hh][2*tx], q1 = sQj[hh][2*tx + 1];
#pragma unroll
            for (int a = 0; a < 2; a++) {
                float2 av = a ? a1 : a0;
#pragma unroll
                for (int b = 0; b < 2; b++) {
                    float2 bv = b ? b1 : b0;
                    float2 qv = b ? q1 : q0;
                    m1[a][b].x += av.x*bv.x + av.y*bv.y;
                    m1[a][b].y += av.x*bv.y - av.y*bv.x;
                    m2[a][b].x += av.x*qv.x + av.y*qv.y;
                    m2[a][b].y += av.x*qv.y - av.y*qv.x;
                }
            }
        }
        __syncthreads();
    }
    int z = blockIdx.z;
#pragma unroll
    for (int a = 0; a < 2; a++)
#pragma unroll
        for (int b = 0; b < 2; b++) {
            int i = i0 + 2*ty + a, j = j0 + 2*tx + b;
            g_M1s[z][i*WW + j] = m1[a][b];
            g_M2s[z][i*WW + j] = m2[a][b];
        }
}

// ---------------- alpha partials: combine K-splits + Smith-scaled divide ----------
__global__ void alpha_part() {
    __shared__ float sr[256], si[256];
    int t = threadIdx.x;
    int k = blockIdx.x*256 + t;
    float2 m1 = make_float2(0.f, 0.f), m2 = make_float2(0.f, 0.f);
#pragma unroll
    for (int z = 0; z < GRAM_SPLIT; z++) {
        float2 p = g_M1s[z][k], q = g_M2s[z][k];
        m1.x += p.x; m1.y += p.y;
        m2.x += q.x; m2.y += q.y;
    }
    float ar, ai;
    if (fabsf(m2.x) >= fabsf(m2.y)) {
        float r = m2.y / m2.x;
        float den = m2.x + m2.y*r;
        ar = (m1.x + m1.y*r) / den;
        ai = (m1.y - m1.x*r) / den;
    } else {
        float r = m2.x / m2.y;
        float den = m2.y + m2.x*r;
        ar = (m1.x*r + m1.y) / den;
        ai = (m1.y*r - m1.x) / den;
    }
    sr[t] = ar; si[t] = ai; __syncthreads();
    for (int o = 128; o > 0; o >>= 1) {
        if (t < o) { sr[t] += sr[t + o]; si[t] += si[t + o]; }
        __syncthreads();
    }
    if (t == 0) g_apart[blockIdx.x] = make_float2(sr[0], si[0]);
}

// ---------------- image += alpha * d  (alpha reduced in-block from partials) ----
__global__ void update_kernel() {
    __shared__ float sr[256], si[256];
    int t = threadIdx.x;
    float ar = 0.f, ai = 0.f;
    for (int k = t; k < ALPHA_BLKS; k += 256) {
        float2 v = g_apart[k];
        ar += v.x; ai += v.y;
    }
    sr[t] = ar; si[t] = ai; __syncthreads();
    for (int o = 128; o > 0; o >>= 1) {
        if (t < o) { sr[t] += sr[t + o]; si[t] += si[t + o]; }
        __syncthreads();
    }
    float alx = sr[0], aly = si[0];
    int idx = blockIdx.x*256 + t;
    if (idx >= HWSZ) return;
    float2 d = g_d[idx], im = g_image[idx];
    im.x += alx*d.x - aly*d.y;
    im.y += alx*d.y + aly*d.x;
    g_image[idx] = im;
}

// ---------------- crop ----------------
__global__ void crop_kernel(float2* __restrict__ out) {
    int t = blockIdx.x*blockDim.x + threadIdx.x;
    if (t >= WW*WW) return;
    int r = t / WW, c = t % WW;
    out[t] = g_image[(r + 64)*WW + c];
}

// ---------------- launch ----------------
extern "C" void kernel_launch(void* const* d_in, const int* in_sizes, int n_in,
                              void* d_out, int out_size) {
    (void)in_sizes; (void)n_in; (void)out_size;
    const float2* b_in  = (const float2*)d_in[0];
    const float2* smaps = (const float2*)d_in[1];
    const float* w0  = (const float*)d_in[2];
    const float* b0  = (const float*)d_in[3];
    const float* w1  = (const float*)d_in[4];
    const float* b1  = (const float*)d_in[5];
    const float* g1  = (const float*)d_in[6];
    const float* be1 = (const float*)d_in[7];
    const float* w2  = (const float*)d_in[8];
    const float* b2  = (const float*)d_in[9];
    const float* g2  = (const float*)d_in[10];
    const float* be2 = (const float*)d_in[11];
    const float* wl  = (const float*)d_in[12];
    const float* bl  = (const float*)d_in[13];
    const float* scl = (const float*)d_in[14];

    const int PW = (HWSZ + 255) / 256;

    ifft_col512<<<dim3(WW, CC), 256>>>(b_in);
    ifft_row384<<<dim3(HH, CC), 128>>>();
    decode_kernel<<<PW, 256>>>(smaps);

    dim3 cgrid(WW/32, HH/16), cblk(32, 4);
    for (int it = 0; it < NITER; it++) {
        // DnCNN with BN+ReLU fused into consumer tile loads
        conv3x3<2, 16, 0, 0><<<cgrid, cblk>>>(0, w0, b0, 0, nullptr, nullptr, nullptr, 0);
        conv3x3<16, 16, 1, 0><<<cgrid, cblk>>>(0, w1, b1, 1, nullptr, nullptr, nullptr, 0); // act0 -> act1 raw
        bn_stats_part<<<dim3(NK, BN_CHUNKS), 256>>>(1);
        conv3x3<16, 16, 1, 1><<<cgrid, cblk>>>(1, w2, b2, 0, g1, be1, nullptr, 0);          // bn1(act1) -> act0 raw
        bn_stats_part<<<dim3(NK, BN_CHUNKS), 256>>>(0);
        conv3x3<16, 2, 2, 1><<<cgrid, cblk>>>(0, wl, bl, 0, g2, be2, scl, it);              // bn2(act0) -> image, d, Qd
        // CG step
        gram_kernel<<<dim3(WW/32, WW/32, GRAM_SPLIT), dim3(16, 16)>>>();
        alpha_part<<<ALPHA_BLKS, 256>>>();
        update_kernel<<<PW, 256>>>();
    }
    crop_kernel<<<(WW*WW + 255)/256, 256>>>((float2*)d_out);
}